// round 15
// baseline (speedup 1.0000x reference)
#include <cuda_runtime.h>
#include <math.h>

// Problem constants (fixed by the reference)
#define N_K        16
#define C_CAT      136          // 16*17/2 upper-tri pairs
#define C_PAD      160          // padded to 32*5 for a uniform unrolled loop
#define DIM        64
#define MU_PITCH   68           // DIM + 4 pad: rows 16B-aligned
#define NROWS      8192         // 512 * 16
#define ROWS_PER_BLK 32         // 16 warps x 2 rows
#define NTHR       512
#define MAIN_BLOCKS (NROWS / ROWS_PER_BLK)   // 256

#define LOG2PI_F   1.8378770664093453f
#define LN2_F      0.6931471805599453f
#define L2E_F      1.4426950408889634f
// Phi-tanh approx: Phi(x) ~= 0.5*(1+tanh(C1*x + C3*x^3))
#define PHI_C1     0.7978845608028654f
#define PHI_C3     0.03567740813712f

// ---- device scratch (static globals; no allocation) ----
__device__ float  d_partials[MAIN_BLOCKS];
__device__ unsigned int d_counter = 0;

typedef unsigned long long ull;

__device__ __forceinline__ float tanh_approx(float x) {
    float r; asm("tanh.approx.f32 %0, %1;" : "=f"(r) : "f"(x)); return r;
}
__device__ __forceinline__ float ex2_approx(float x) {
    float r; asm("ex2.approx.f32 %0, %1;" : "=f"(r) : "f"(x)); return r;
}
// f32x2 packed helpers (sm_103a)
__device__ __forceinline__ ull pk2(float a, float b) {
    ull r; asm("mov.b64 %0, {%1,%2};" : "=l"(r)
               : "r"(__float_as_uint(a)), "r"(__float_as_uint(b))); return r;
}
__device__ __forceinline__ ull dup2(float a) { return pk2(a, a); }
__device__ __forceinline__ void upk2(ull v, float& a, float& b) {
    unsigned int x, y; asm("mov.b64 {%0,%1}, %2;" : "=r"(x), "=r"(y) : "l"(v));
    a = __uint_as_float(x); b = __uint_as_float(y);
}
__device__ __forceinline__ ull add2(ull a, ull b) {
    ull r; asm("add.rn.f32x2 %0, %1, %2;" : "=l"(r) : "l"(a), "l"(b)); return r;
}
__device__ __forceinline__ ull mul2(ull a, ull b) {
    ull r; asm("mul.rn.f32x2 %0, %1, %2;" : "=l"(r) : "l"(a), "l"(b)); return r;
}
__device__ __forceinline__ ull fma2p(ull a, ull b, ull c) {
    ull r; asm("fma.rn.f32x2 %0, %1, %2, %3;" : "=l"(r) : "l"(a), "l"(b), "l"(c)); return r;
}

// ---------------------------------------------------------------------------
// SINGLE fused kernel. 32 rows/block (512 thr, 16 warps), two rows per warp.
// log2-domain hot loop; g values staged in smem (conflict-free LDS replaces
// the 20 dependent hot-loop shuffles); constants hoisted to registers.
// ---------------------------------------------------------------------------
__global__ __launch_bounds__(NTHR) void fused_kernel(const float* __restrict__ z,
                                                     const float* __restrict__ pi,
                                                     const float* __restrict__ mu,
                                                     float* __restrict__ out)
{
    __shared__ float  mu_t[N_K][MU_PITCH];          // transposed mu
    __shared__ float  z_s [ROWS_PER_BLK][DIM];      // 8 KB
    __shared__ float  g_sL[ROWS_PER_BLK][N_K];      // g * log2e per row
    __shared__ float  g_gram[N_K][N_K + 1];         // Gram(mu_k, mu_j)
    __shared__ float4 c4_s[C_PAD];                  // {k1L, recipX, s, baseC2}
    __shared__ int    ab_s[C_PAD];                  // A | B<<8
    __shared__ float  rowres[ROWS_PER_BLK];
    __shared__ float  red[NTHR];
    __shared__ int    s_is_last;

    const int t = threadIdx.x;
    const int w = t >> 5;        // warp 0..15; handles rows 2w, 2w+1
    const int l = t & 31;

    // ---- vectorized z prefetch: lane l loads float4 l of the 2-row span ----
    const int row0 = blockIdx.x * ROWS_PER_BLK;
    const float4* zrow4 = (const float4*)(z + (row0 + 2 * w) * DIM);
    const float4 zv = zrow4[l];          // lanes 0-15: row 2w; 16-31: row 2w+1

    // stage mu transposed (2 iterations at 512 threads)
    for (int i = t; i < DIM * N_K; i += NTHR) {
        const int d = i >> 4, k = i & 15;           // mu is [d][k]
        mu_t[k][d] = mu[i];
    }
    // stage z (one STS.128 per lane; rows are contiguous in z_s)
    ((float4*)&z_s[2 * w][0])[l] = zv;
    // padding category slots
    if (t >= C_CAT && t < C_PAD) {
        c4_s[t] = make_float4(0.f, 0.f, 20.f, -1e30f);
        ab_s[t] = 0;
    }

    // warp-local softmax denominator -- only warps 0..4 (feed threads < 136)
    float lgden = 0.f;
    if (w < 5) {
        const float v0 = pi[l], v1 = pi[l + 32], v2 = pi[l + 64], v3 = pi[l + 96];
        const float v4 = (l < 8) ? pi[128 + l] : -INFINITY;
        float mx = fmaxf(fmaxf(fmaxf(v0, v1), fmaxf(v2, v3)), v4);
        #pragma unroll
        for (int o = 16; o; o >>= 1) mx = fmaxf(mx, __shfl_xor_sync(0xffffffffu, mx, o));
        float sm = __expf(v0 - mx) + __expf(v1 - mx) + __expf(v2 - mx) + __expf(v3 - mx)
                 + ((l < 8) ? __expf(v4 - mx) : 0.f);
        #pragma unroll
        for (int o = 16; o; o >>= 1) sm += __shfl_xor_sync(0xffffffffu, sm, o);
        lgden = mx + __logf(sm);
    }

    // 0.5*|z|^2: per-lane float4 self-dot, 4-step half-butterfly, 1 exchange
    float pown = (zv.x * zv.x + zv.y * zv.y) + (zv.z * zv.z + zv.w * zv.w);
    #pragma unroll
    for (int o = 1; o <= 8; o <<= 1) pown += __shfl_xor_sync(0xffffffffu, pown, o);
    const float poth = __shfl_xor_sync(0xffffffffu, pown, 16);
    const float p0 = (l < 16) ? pown : poth;        // row 2w
    const float p1 = (l < 16) ? poth : pown;        // row 2w+1

    __syncthreads();                                 // mu_t & z_s ready

    // ---- Gram pass: thread c (<136) computes dot(mu_A, mu_B), one pass ----
    int Ad = 0, Bd = 0;
    if (t < C_CAT) {
        const float cf = (float)t;
        Ad = (int)floorf((33.0f - sqrtf(fmaf(-8.0f, cf, 1089.0f))) * 0.5f);
        Bd = t - ((33 - Ad) * Ad >> 1) + Ad;         // f(A) = A*(33-A)/2

        const float4* ma = (const float4*)&mu_t[Ad][0];
        const float4* mb = (const float4*)&mu_t[Bd][0];
        float a0 = 0.f, a1 = 0.f, a2 = 0.f, a3 = 0.f;
        #pragma unroll
        for (int j = 0; j < 16; ++j) {
            const float4 fa = ma[j];
            const float4 fb = mb[j];
            a0 = fmaf(fa.x, fb.x, a0); a1 = fmaf(fa.y, fb.y, a1);
            a2 = fmaf(fa.z, fb.z, a2); a3 = fmaf(fa.w, fb.w, a3);
        }
        const float g = (a0 + a1) + (a2 + a3);
        g_gram[Ad][Bd] = g;
        g_gram[Bd][Ad] = g;
    }
    __syncthreads();                                 // Gram ready

    // ---- per-category constants from Gram (log2 domain) ----
    if (t < C_CAT) {
        const float GAA = g_gram[Ad][Ad];
        const float GAB = g_gram[Ad][Bd];
        const float GBB = g_gram[Bd][Bd];
        const float invsig = (GAA - 2.0f * GAB) + GBB;
        const float lp = -32.0f * LOG2PI_F + (__ldg(&pi[t]) - lgden);

        float baseC, recipX, s, k1L;
        if (Ad == Bd) {                      // diag: inv_sig == 0 exactly
            baseC = lp - 0.5f * GBB; recipX = 0.f; s = 20.f; k1L = 0.f;
        } else {
            const float clip_is = fminf(fmaxf(invsig, 1e-12f), 1e30f);
            s      = sqrtf(clip_is);
            baseC  = lp + 0.5f * (LOG2PI_F - __logf(clip_is)) - LN2_F - 0.5f * GBB;
            recipX = (1.0f / invsig) * (1.0f / L2E_F);
            k1L    = (GBB - GAB) * L2E_F;    // dot(alpha, mu_B) * log2e
        }
        c4_s[t] = make_float4(k1L, recipX, s, baseC * L2E_F);
        ab_s[t] = Ad | (Bd << 8);
    }
    __syncthreads();                                 // constants ready

    // ---- hoist this lane's 5 constant sets; LDS latency hides under g-dot ----
    float4 c4r[5];
    int    abr[5];
    #pragma unroll
    for (int i = 0; i < 5; ++i) {
        c4r[i] = c4_s[l + 32 * i];
        abr[i] = ab_s[l + 32 * i];
    }

    // g-dot for both rows: mu loaded once; results prescaled by log2e
    {
        const int k = l & 15, h = l >> 4;
        const float4* mr  = (const float4*)&mu_t[k][h * 32];
        const float4* zr0 = (const float4*)&z_s[2 * w][h * 32];
        const float4* zr1 = (const float4*)&z_s[2 * w + 1][h * 32];
        float a0 = 0.f, a1 = 0.f, a2 = 0.f, a3 = 0.f;
        float b0 = 0.f, b1 = 0.f, b2 = 0.f, b3 = 0.f;
        #pragma unroll
        for (int j = 0; j < 8; ++j) {
            const float4 mv = mr[j];
            const float4 q0 = zr0[j];
            const float4 q1 = zr1[j];
            a0 = fmaf(q0.x, mv.x, a0); a1 = fmaf(q0.y, mv.y, a1);
            a2 = fmaf(q0.z, mv.z, a2); a3 = fmaf(q0.w, mv.w, a3);
            b0 = fmaf(q1.x, mv.x, b0); b1 = fmaf(q1.y, mv.y, b1);
            b2 = fmaf(q1.z, mv.z, b2); b3 = fmaf(q1.w, mv.w, b3);
        }
        float acc0 = (a0 + a1) + (a2 + a3);
        float acc1 = (b0 + b1) + (b2 + b3);
        acc0 += __shfl_xor_sync(0xffffffffu, acc0, 16);
        acc1 += __shfl_xor_sync(0xffffffffu, acc1, 16);
        if (l < N_K) {                       // stage g*log2e to smem
            g_sL[2 * w][l]     = acc0 * L2E_F;
            g_sL[2 * w + 1][l] = acc1 * L2E_F;
        }
    }
    __syncwarp();

    // ---- bC2max = max_c baseC2 (from hoisted registers) ----
    float bmax = c4r[0].w;
    #pragma unroll
    for (int i = 1; i < 5; ++i) bmax = fmaxf(bmax, c4r[i].w);
    #pragma unroll
    for (int o = 16; o; o >>= 1) bmax = fmaxf(bmax, __shfl_xor_sync(0xffffffffu, bmax, o));
    const float bC2max = bmax;

    // packed loop-invariants
    const ull NEG1  = dup2(-1.0f);
    const ull HALF2 = dup2(0.5f);
    const ull C1_2  = dup2(PHI_C1);
    const ull C3_2  = dup2(PHI_C3);
    const ull nSh2  = pk2(-fmaf(0.5f * p0, L2E_F, bC2max),
                          -fmaf(0.5f * p1, L2E_F, bC2max));
    const float* g0 = &g_sL[2 * w][0];
    const float* g1 = &g_sL[2 * w + 1][0];

    // ---- hot loop: 5 categories, both rows packed; g via conflict-free LDS ----
    float ss0 = 0.f, ss1 = 0.f;
    #pragma unroll
    for (int i = 0; i < 5; ++i) {
        const float4 q4 = c4r[i];                   // k1L, recipX, s, baseC2
        const int ab = abr[i];
        const int Ai = ab & 15, Bi = (ab >> 8) & 15;
        const ull gA2 = pk2(g0[Ai], g1[Ai]);
        const ull gB2 = pk2(g0[Bi], g1[Bi]);

        const ull k1_2 = dup2(q4.x);
        const ull rc2  = dup2(q4.y);
        const ull s2   = dup2(q4.z);
        const ull bc2  = dup2(q4.w);

        const ull deL = add2(fma2p(gB2, NEG1, k1_2), gA2);  // deltaL
        const ull nu2 = mul2(deL, rc2);                     // true nu
        const ull bg  = add2(add2(bc2, gB2), nSh2);         // baseC2 + gBL - shift
        const ull xs  = fma2p(mul2(deL, HALF2), nu2, bg);   // exponent (log2)

        const ull ns2  = mul2(nu2, s2);
        const ull nns2 = mul2(ns2, NEG1);                   // eta2 = -nu*s
        const ull e1_2 = add2(s2, nns2);                    // eta1 = (1-nu)*s
        const ull u1_2 = mul2(e1_2, fma2p(C3_2, mul2(e1_2, e1_2), C1_2));
        const ull u2_2 = mul2(nns2, fma2p(C3_2, mul2(nns2, nns2), C1_2));

        float u1a, u1b, u2a, u2b, x0, x1;
        upk2(u1_2, u1a, u1b);
        upk2(u2_2, u2a, u2b);
        upk2(xs, x0, x1);
        const float D0 = fmaxf(tanh_approx(u1a) - tanh_approx(u2a), 2e-16f);
        const float D1 = fmaxf(tanh_approx(u1b) - tanh_approx(u2b), 2e-16f);
        ss0 = fmaf(ex2_approx(x0), D0, ss0);
        ss1 = fmaf(ex2_approx(x1), D1, ss1);
    }

    // warp sum of ss (both rows)
    #pragma unroll
    for (int o = 16; o; o >>= 1) {
        ss0 += __shfl_xor_sync(0xffffffffu, ss0, o);
        ss1 += __shfl_xor_sync(0xffffffffu, ss1, o);
    }

    // rowres = bC2max*ln2 + log(ss)   (z2h cancels exactly)
    if (l == 0) {
        const float bnat = bC2max * LN2_F;
        rowres[2 * w]     = bnat + __logf(fmaxf(ss0, 1e-37f));
        rowres[2 * w + 1] = bnat + __logf(fmaxf(ss1, 1e-37f));
    }
    __syncthreads();

    // ---- per-block partial + last-block-done finalize ----
    if (t == 0) {
        float s = 0.f;
        #pragma unroll
        for (int r = 0; r < ROWS_PER_BLK; ++r) s += rowres[r];
        d_partials[blockIdx.x] = s;
        __threadfence();
        const unsigned int ticket = atomicAdd(&d_counter, 1u);
        s_is_last = (ticket == (unsigned)(gridDim.x - 1));
    }
    __syncthreads();

    if (s_is_last) {
        float s = 0.f;
        if (t < MAIN_BLOCKS / 4) {
            const float4 v = __ldcg(((const float4*)d_partials) + t);
            s = (v.x + v.y) + (v.z + v.w);
        }
        red[t] = s; __syncthreads();
        for (int o = NTHR / 2; o; o >>= 1) { if (t < o) red[t] += red[t + o]; __syncthreads(); }
        if (t == 0) {
            out[0] = red[0] * (1.0f / (float)NROWS);
            d_counter = 0;                 // reset for next graph replay
        }
    }
}

// ---------------------------------------------------------------------------
extern "C" void kernel_launch(void* const* d_in, const int* in_sizes, int n_in,
                              void* d_out, int out_size)
{
    (void)in_sizes; (void)n_in; (void)out_size;
    const float* z  = (const float*)d_in[0];
    const float* pi = (const float*)d_in[1];
    const float* mu = (const float*)d_in[2];
    float* out = (float*)d_out;

    fused_kernel<<<MAIN_BLOCKS, NTHR>>>(z, pi, mu, out);
}

// round 16
// speedup vs baseline: 1.0201x; 1.0201x over previous
#include <cuda_runtime.h>
#include <math.h>

// Problem constants (fixed by the reference)
#define N_K        16
#define C_CAT      136          // 16*17/2 upper-tri pairs
#define C_PAD      160          // padded to 32*5 for a uniform unrolled loop
#define DIM        64
#define MU_PITCH   68           // DIM + 4 pad: rows 16B-aligned
#define NROWS      8192         // 512 * 16
#define ROWS_PER_BLK 32         // 16 warps x 2 rows
#define NTHR       512
#define MAIN_BLOCKS (NROWS / ROWS_PER_BLK)   // 256

#define LOG2PI_F   1.8378770664093453f
#define LN2_F      0.6931471805599453f
#define L2E_F      1.4426950408889634f
// Phi-tanh approx: Phi(x) ~= 0.5*(1+tanh(C1*x + C3*x^3))
#define PHI_C1     0.7978845608028654f
#define PHI_C3     0.03567740813712f

// ---- device scratch (static globals; no allocation) ----
__device__ float  d_partials[MAIN_BLOCKS];
__device__ unsigned int d_counter = 0;

typedef unsigned long long ull;

__device__ __forceinline__ float tanh_approx(float x) {
    float r; asm("tanh.approx.f32 %0, %1;" : "=f"(r) : "f"(x)); return r;
}
__device__ __forceinline__ float ex2_approx(float x) {
    float r; asm("ex2.approx.f32 %0, %1;" : "=f"(r) : "f"(x)); return r;
}
// f32x2 packed helpers (sm_103a)
__device__ __forceinline__ ull pk2(float a, float b) {
    ull r; asm("mov.b64 %0, {%1,%2};" : "=l"(r)
               : "r"(__float_as_uint(a)), "r"(__float_as_uint(b))); return r;
}
__device__ __forceinline__ ull dup2(float a) { return pk2(a, a); }
__device__ __forceinline__ void upk2(ull v, float& a, float& b) {
    unsigned int x, y; asm("mov.b64 {%0,%1}, %2;" : "=r"(x), "=r"(y) : "l"(v));
    a = __uint_as_float(x); b = __uint_as_float(y);
}
__device__ __forceinline__ ull add2(ull a, ull b) {
    ull r; asm("add.rn.f32x2 %0, %1, %2;" : "=l"(r) : "l"(a), "l"(b)); return r;
}
__device__ __forceinline__ ull mul2(ull a, ull b) {
    ull r; asm("mul.rn.f32x2 %0, %1, %2;" : "=l"(r) : "l"(a), "l"(b)); return r;
}
__device__ __forceinline__ ull fma2p(ull a, ull b, ull c) {
    ull r; asm("fma.rn.f32x2 %0, %1, %2, %3;" : "=l"(r) : "l"(a), "l"(b), "l"(c)); return r;
}

// ---------------------------------------------------------------------------
// SINGLE fused kernel. 32 rows/block (512 thr, 16 warps), two rows per warp.
// log2-domain hot loop; g staged in smem (conflict-free LDS, no hot shuffles).
// __launch_bounds__(512, 3): cap regs at 40 -> 3 resident blocks/SM (48 warps)
// to raise issue rate on this dependency-latency-bound kernel.
// ---------------------------------------------------------------------------
__global__ __launch_bounds__(NTHR, 3) void fused_kernel(const float* __restrict__ z,
                                                        const float* __restrict__ pi,
                                                        const float* __restrict__ mu,
                                                        float* __restrict__ out)
{
    __shared__ float  mu_t[N_K][MU_PITCH];          // transposed mu
    __shared__ float  z_s [ROWS_PER_BLK][DIM];      // 8 KB
    __shared__ float  g_sL[ROWS_PER_BLK][N_K];      // g * log2e per row
    __shared__ float  g_gram[N_K][N_K + 1];         // Gram(mu_k, mu_j)
    __shared__ float4 c4_s[C_PAD];                  // {k1L, recipX, s, baseC2}
    __shared__ int    ab_s[C_PAD];                  // A | B<<8
    __shared__ float  rowres[ROWS_PER_BLK];
    __shared__ float  red[NTHR];
    __shared__ int    s_is_last;

    const int t = threadIdx.x;
    const int w = t >> 5;        // warp 0..15; handles rows 2w, 2w+1
    const int l = t & 31;

    // ---- vectorized z prefetch: lane l loads float4 l of the 2-row span ----
    const int row0 = blockIdx.x * ROWS_PER_BLK;
    const float4* zrow4 = (const float4*)(z + (row0 + 2 * w) * DIM);
    const float4 zv = zrow4[l];          // lanes 0-15: row 2w; 16-31: row 2w+1

    // stage mu transposed (2 iterations at 512 threads)
    for (int i = t; i < DIM * N_K; i += NTHR) {
        const int d = i >> 4, k = i & 15;           // mu is [d][k]
        mu_t[k][d] = mu[i];
    }
    // stage z (one STS.128 per lane; rows are contiguous in z_s)
    ((float4*)&z_s[2 * w][0])[l] = zv;
    // padding category slots
    if (t >= C_CAT && t < C_PAD) {
        c4_s[t] = make_float4(0.f, 0.f, 20.f, -1e30f);
        ab_s[t] = 0;
    }

    // warp-local softmax denominator -- only warps 0..4 (feed threads < 136)
    float lgden = 0.f;
    if (w < 5) {
        const float v0 = pi[l], v1 = pi[l + 32], v2 = pi[l + 64], v3 = pi[l + 96];
        const float v4 = (l < 8) ? pi[128 + l] : -INFINITY;
        float mx = fmaxf(fmaxf(fmaxf(v0, v1), fmaxf(v2, v3)), v4);
        #pragma unroll
        for (int o = 16; o; o >>= 1) mx = fmaxf(mx, __shfl_xor_sync(0xffffffffu, mx, o));
        float sm = __expf(v0 - mx) + __expf(v1 - mx) + __expf(v2 - mx) + __expf(v3 - mx)
                 + ((l < 8) ? __expf(v4 - mx) : 0.f);
        #pragma unroll
        for (int o = 16; o; o >>= 1) sm += __shfl_xor_sync(0xffffffffu, sm, o);
        lgden = mx + __logf(sm);
    }

    // 0.5*|z|^2: per-lane float4 self-dot, 4-step half-butterfly, 1 exchange
    float pown = (zv.x * zv.x + zv.y * zv.y) + (zv.z * zv.z + zv.w * zv.w);
    #pragma unroll
    for (int o = 1; o <= 8; o <<= 1) pown += __shfl_xor_sync(0xffffffffu, pown, o);
    const float poth = __shfl_xor_sync(0xffffffffu, pown, 16);
    const float p0 = (l < 16) ? pown : poth;        // row 2w
    const float p1 = (l < 16) ? poth : pown;        // row 2w+1

    __syncthreads();                                 // mu_t & z_s ready

    // ---- Gram pass: thread c (<136) computes dot(mu_A, mu_B), one pass ----
    int Ad = 0, Bd = 0;
    if (t < C_CAT) {
        const float cf = (float)t;
        Ad = (int)floorf((33.0f - sqrtf(fmaf(-8.0f, cf, 1089.0f))) * 0.5f);
        Bd = t - ((33 - Ad) * Ad >> 1) + Ad;         // f(A) = A*(33-A)/2

        const float4* ma = (const float4*)&mu_t[Ad][0];
        const float4* mb = (const float4*)&mu_t[Bd][0];
        float a0 = 0.f, a1 = 0.f, a2 = 0.f, a3 = 0.f;
        #pragma unroll
        for (int j = 0; j < 16; ++j) {
            const float4 fa = ma[j];
            const float4 fb = mb[j];
            a0 = fmaf(fa.x, fb.x, a0); a1 = fmaf(fa.y, fb.y, a1);
            a2 = fmaf(fa.z, fb.z, a2); a3 = fmaf(fa.w, fb.w, a3);
        }
        const float g = (a0 + a1) + (a2 + a3);
        g_gram[Ad][Bd] = g;
        g_gram[Bd][Ad] = g;
    }
    __syncthreads();                                 // Gram ready

    // ---- per-category constants from Gram (log2 domain) ----
    if (t < C_CAT) {
        const float GAA = g_gram[Ad][Ad];
        const float GAB = g_gram[Ad][Bd];
        const float GBB = g_gram[Bd][Bd];
        const float invsig = (GAA - 2.0f * GAB) + GBB;
        const float lp = -32.0f * LOG2PI_F + (__ldg(&pi[t]) - lgden);

        float baseC, recipX, s, k1L;
        if (Ad == Bd) {                      // diag: inv_sig == 0 exactly
            baseC = lp - 0.5f * GBB; recipX = 0.f; s = 20.f; k1L = 0.f;
        } else {
            const float clip_is = fminf(fmaxf(invsig, 1e-12f), 1e30f);
            s      = sqrtf(clip_is);
            baseC  = lp + 0.5f * (LOG2PI_F - __logf(clip_is)) - LN2_F - 0.5f * GBB;
            recipX = (1.0f / invsig) * (1.0f / L2E_F);
            k1L    = (GBB - GAB) * L2E_F;    // dot(alpha, mu_B) * log2e
        }
        c4_s[t] = make_float4(k1L, recipX, s, baseC * L2E_F);
        ab_s[t] = Ad | (Bd << 8);
    }
    __syncthreads();                                 // constants ready

    // g-dot for both rows: mu loaded once; results prescaled by log2e
    {
        const int k = l & 15, h = l >> 4;
        const float4* mr  = (const float4*)&mu_t[k][h * 32];
        const float4* zr0 = (const float4*)&z_s[2 * w][h * 32];
        const float4* zr1 = (const float4*)&z_s[2 * w + 1][h * 32];
        float a0 = 0.f, a1 = 0.f, a2 = 0.f, a3 = 0.f;
        float b0 = 0.f, b1 = 0.f, b2 = 0.f, b3 = 0.f;
        #pragma unroll
        for (int j = 0; j < 8; ++j) {
            const float4 mv = mr[j];
            const float4 q0 = zr0[j];
            const float4 q1 = zr1[j];
            a0 = fmaf(q0.x, mv.x, a0); a1 = fmaf(q0.y, mv.y, a1);
            a2 = fmaf(q0.z, mv.z, a2); a3 = fmaf(q0.w, mv.w, a3);
            b0 = fmaf(q1.x, mv.x, b0); b1 = fmaf(q1.y, mv.y, b1);
            b2 = fmaf(q1.z, mv.z, b2); b3 = fmaf(q1.w, mv.w, b3);
        }
        float acc0 = (a0 + a1) + (a2 + a3);
        float acc1 = (b0 + b1) + (b2 + b3);
        acc0 += __shfl_xor_sync(0xffffffffu, acc0, 16);
        acc1 += __shfl_xor_sync(0xffffffffu, acc1, 16);
        if (l < N_K) {                       // stage g*log2e to smem
            g_sL[2 * w][l]     = acc0 * L2E_F;
            g_sL[2 * w + 1][l] = acc1 * L2E_F;
        }
    }
    __syncwarp();

    // ---- bC2max = max_c baseC2 ----
    float bmax = c4_s[l].w;
    #pragma unroll
    for (int i = 1; i < 5; ++i) bmax = fmaxf(bmax, c4_s[l + 32 * i].w);
    #pragma unroll
    for (int o = 16; o; o >>= 1) bmax = fmaxf(bmax, __shfl_xor_sync(0xffffffffu, bmax, o));
    const float bC2max = bmax;

    // packed loop-invariants
    const ull NEG1  = dup2(-1.0f);
    const ull HALF2 = dup2(0.5f);
    const ull C1_2  = dup2(PHI_C1);
    const ull C3_2  = dup2(PHI_C3);
    const ull nSh2  = pk2(-fmaf(0.5f * p0, L2E_F, bC2max),
                          -fmaf(0.5f * p1, L2E_F, bC2max));
    const float* g0 = &g_sL[2 * w][0];
    const float* g1 = &g_sL[2 * w + 1][0];

    // ---- hot loop: 5 categories, both rows packed; g via conflict-free LDS ----
    float ss0 = 0.f, ss1 = 0.f;
    #pragma unroll
    for (int i = 0; i < 5; ++i) {
        const int c = l + 32 * i;
        const float4 q4 = c4_s[c];                  // k1L, recipX, s, baseC2
        const int ab = ab_s[c];
        const int Ai = ab & 15, Bi = (ab >> 8) & 15;
        const ull gA2 = pk2(g0[Ai], g1[Ai]);
        const ull gB2 = pk2(g0[Bi], g1[Bi]);

        const ull k1_2 = dup2(q4.x);
        const ull rc2  = dup2(q4.y);
        const ull s2   = dup2(q4.z);
        const ull bc2  = dup2(q4.w);

        const ull deL = add2(fma2p(gB2, NEG1, k1_2), gA2);  // deltaL
        const ull nu2 = mul2(deL, rc2);                     // true nu
        const ull bg  = add2(add2(bc2, gB2), nSh2);         // baseC2 + gBL - shift
        const ull xs  = fma2p(mul2(deL, HALF2), nu2, bg);   // exponent (log2)

        const ull ns2  = mul2(nu2, s2);
        const ull nns2 = mul2(ns2, NEG1);                   // eta2 = -nu*s
        const ull e1_2 = add2(s2, nns2);                    // eta1 = (1-nu)*s
        const ull u1_2 = mul2(e1_2, fma2p(C3_2, mul2(e1_2, e1_2), C1_2));
        const ull u2_2 = mul2(nns2, fma2p(C3_2, mul2(nns2, nns2), C1_2));

        float u1a, u1b, u2a, u2b, x0, x1;
        upk2(u1_2, u1a, u1b);
        upk2(u2_2, u2a, u2b);
        upk2(xs, x0, x1);
        const float D0 = fmaxf(tanh_approx(u1a) - tanh_approx(u2a), 2e-16f);
        const float D1 = fmaxf(tanh_approx(u1b) - tanh_approx(u2b), 2e-16f);
        ss0 = fmaf(ex2_approx(x0), D0, ss0);
        ss1 = fmaf(ex2_approx(x1), D1, ss1);
    }

    // warp sum of ss (both rows)
    #pragma unroll
    for (int o = 16; o; o >>= 1) {
        ss0 += __shfl_xor_sync(0xffffffffu, ss0, o);
        ss1 += __shfl_xor_sync(0xffffffffu, ss1, o);
    }

    // rowres = bC2max*ln2 + log(ss)   (z2h cancels exactly)
    if (l == 0) {
        const float bnat = bC2max * LN2_F;
        rowres[2 * w]     = bnat + __logf(fmaxf(ss0, 1e-37f));
        rowres[2 * w + 1] = bnat + __logf(fmaxf(ss1, 1e-37f));
    }
    __syncthreads();

    // ---- per-block partial + last-block-done finalize ----
    if (t == 0) {
        float s = 0.f;
        #pragma unroll
        for (int r = 0; r < ROWS_PER_BLK; ++r) s += rowres[r];
        d_partials[blockIdx.x] = s;
        __threadfence();
        const unsigned int ticket = atomicAdd(&d_counter, 1u);
        s_is_last = (ticket == (unsigned)(gridDim.x - 1));
    }
    __syncthreads();

    if (s_is_last) {
        float s = 0.f;
        if (t < MAIN_BLOCKS / 4) {
            const float4 v = __ldcg(((const float4*)d_partials) + t);
            s = (v.x + v.y) + (v.z + v.w);
        }
        red[t] = s; __syncthreads();
        for (int o = NTHR / 2; o; o >>= 1) { if (t < o) red[t] += red[t + o]; __syncthreads(); }
        if (t == 0) {
            out[0] = red[0] * (1.0f / (float)NROWS);
            d_counter = 0;                 // reset for next graph replay
        }
    }
}

// ---------------------------------------------------------------------------
extern "C" void kernel_launch(void* const* d_in, const int* in_sizes, int n_in,
                              void* d_out, int out_size)
{
    (void)in_sizes; (void)n_in; (void)out_size;
    const float* z  = (const float*)d_in[0];
    const float* pi = (const float*)d_in[1];
    const float* mu = (const float*)d_in[2];
    float* out = (float*)d_out;

    fused_kernel<<<MAIN_BLOCKS, NTHR>>>(z, pi, mu, out);
}